// round 6
// baseline (speedup 1.0000x reference)
#include <cuda_runtime.h>

// BeamSearch_11295763988573 — GB300 (sm_103a)
//
// Output layout (float32, tuple flattened in order):
//   [0]                                   done        (1 elem)
//   [1, 1+B*N)                            new_mask    (B,N)
//   [1+B*N, 1+B*N+B*N*N)                  adj         (B,N,N)
//   then future_actions (B), present_time_new (B), step_mask (B)

static constexpr int B_ = 64;
static constexpr int N_ = 1024;
static constexpr int TI = 16;   // i-rows per block in adj kernel
static constexpr int BG = 16;   // b's per block in adj kernel

static constexpr long long OFF_NM  = 1;
static constexpr long long OFF_ADJ = 1 + (long long)B_ * N_;                 // 65537
static constexpr long long OFF_FA  = OFF_ADJ + (long long)B_ * N_ * N_;      // 67174401
static constexpr long long OFF_PT  = OFF_FA + B_;
static constexpr long long OFF_SM  = OFF_PT + B_;

// Per-(b,j) constants for the adj kernel: {closing, durat, dlast, new_mask}
__device__ float4 g_q[B_ * N_];
// Per-(b,i) constants: {fpresent, opening}
__device__ float2 g_fo[B_ * N_];

// ---------------------------------------------------------------------------
// Kernel 1: new_mask, fpresent, per-j constants, small outputs.
// Exact elementwise reproduction of the reference arithmetic.
// ---------------------------------------------------------------------------
__global__ __launch_bounds__(256) void bs_prep(
    const float4* __restrict__ inp4,   // (B,N,4): x=open, y=close, z=dur, w=ttime
    const float*  __restrict__ dist,   // (N,N)
    const float*  __restrict__ mask,   // (B,N)
    const float*  __restrict__ ptime,  // (B,1)
    const int*    __restrict__ pres,   // (B,)
    const int*    __restrict__ fut,    // (B,)
    float* __restrict__ out)
{
    const int b  = blockIdx.x;
    const int pa = pres[b];
    const float pt = ptime[b];
    const float tt0 = __ldg(reinterpret_cast<const float*>(inp4) + 3); // inputs[0,0,ARR]

    for (int j = threadIdx.x; j < N_; j += blockDim.x) {
        const float4 in = inp4[b * N_ + j];
        const float arrive = __ldg(&dist[pa * N_ + j]) + pt;
        const float wait   = fmaxf(0.0f, in.x - arrive);
        const float s1     = arrive + wait;                 // arrive + wait (ref order)
        const float dl     = __ldg(&dist[j * N_ + (N_ - 1)]);
        const bool c1 = (s1 <= in.y);
        const bool c2 = (((s1 + in.z) + dl) <= tt0);        // ((arr+wait)+dur)+dlast <= tt
        float m = mask[b * N_ + j];
        if (j == pa) m = 0.0f;
        const float nm = (c1 && c2) ? m : 0.0f;

        out[OFF_NM + (long long)b * N_ + j] = nm;
        g_q [b * N_ + j] = make_float4(in.y, in.z, dl, nm);
        g_fo[b * N_ + j] = make_float2(s1 + in.z, in.x);    // fpresent, opening
    }

    if (threadIdx.x == 0) {
        const int fa = fut[b];
        const float4 infa = inp4[b * N_ + fa];
        const float arrj = __ldg(&dist[pa * N_ + fa]) + pt;
        const float wj   = fmaxf(0.0f, infa.x - arrj);
        out[OFF_FA + b] = (float)fa;
        out[OFF_PT + b] = (arrj + wj) + infa.z;
        out[OFF_SM + b] = 1.0f;
    }
}

// ---------------------------------------------------------------------------
// Kernel: done = !any(new_mask[:, -1] > 0)
// ---------------------------------------------------------------------------
__global__ void bs_done(float* __restrict__ out)
{
    const int b = threadIdx.x;  // 64 threads
    const int v = (out[OFF_NM + (long long)b * N_ + (N_ - 1)] > 0.0f) ? 1 : 0;
    const int any = __syncthreads_or(v);
    if (b == 0) out[0] = any ? 0.0f : 1.0f;
}

// ---------------------------------------------------------------------------
// Kernel 2: adj (B,N,N). HBM-write-bound.
// adj[b,i,j] = (i==j) ? 1 : new_mask[b,j] * a1 * a2, with
//   arr2 = dist[i,j] + fpresent[b,i]
//   s    = fmax(arr2, open[b,i])       (outcome-exact vs arr2 + max(0, open-arr2))
//   a1   = s <= close[b,j]
//   a2   = ((s + dur[b,j]) + dlast[j]) <= ttime[b]
//
// Alignment: out base for adj is ≡ 4 bytes (mod 16), so thread t owns the
// ALIGNED output quad j∈[4t+3, 4t+7). Its dist values come from the aligned
// quad [4t+4,4t+8) plus d[4t+3] via __shfl_up from the neighbor lane.
// Thread 255 handles straggler columns {0,1,2,1023}.
// ---------------------------------------------------------------------------
__device__ __forceinline__ float adjval(float d, float fp, float opn,
                                        float4 q, float tt)
{
    const float arr2 = d + fp;
    const float s    = fmaxf(arr2, opn);
    const float s2   = (s + q.y) + q.z;
    return (s <= q.x && s2 <= tt) ? q.w : 0.0f;
}

__global__ __launch_bounds__(256) void bs_adj(
    const float* __restrict__ dist,
    const float* __restrict__ inpf,    // raw float view of inputs
    float* __restrict__ out)
{
    const int t   = threadIdx.x;            // 0..255
    const int ib0 = blockIdx.x * TI;
    const int b0  = blockIdx.y * BG;
    const bool main_thr = (t < 255);
    const int j0 = 4 * t + 3;               // first owned output column (t<255)

    for (int bb = 0; bb < BG; ++bb) {
        const int b = b0 + bb;
        const float tt = __ldg(inpf + (long long)b * N_ * 4 + 3);  // inputs[b,0,ARR]

        float4 q0, q1, q2, q3;
        if (main_thr) {
            q0 = g_q[b * N_ + j0];
            q1 = g_q[b * N_ + j0 + 1];
            q2 = g_q[b * N_ + j0 + 2];
            q3 = g_q[b * N_ + j0 + 3];
        } else {
            q0 = g_q[b * N_ + 0];
            q1 = g_q[b * N_ + 1];
            q2 = g_q[b * N_ + 2];
            q3 = g_q[b * N_ + N_ - 1];
        }

#pragma unroll 4
        for (int ii = 0; ii < TI; ++ii) {
            const int i = ib0 + ii;
            const float2 fo = g_fo[b * N_ + i];
            const float fp = fo.x, opn = fo.y;

            float4 dq;
            if (main_thr) {
                dq = *reinterpret_cast<const float4*>(dist + (long long)i * N_ + 4 * t + 4);
            } else {
                dq = *reinterpret_cast<const float4*>(dist + (long long)i * N_);  // d[0..3]
            }
            // d[4t+3] lives in the previous lane's quad (.w). Lane31's value
            // conveniently is d[1023] for thread 255.
            float dprev = __shfl_up_sync(0xFFFFFFFFu, dq.w, 1);

            if (main_thr) {
                if ((t & 31) == 0)  // warp-edge lane: fetch d[4t+3] directly
                    dprev = __ldg(dist + (long long)i * N_ + j0);

                float v0 = adjval(dprev, fp, opn, q0, tt);
                float v1 = adjval(dq.x,  fp, opn, q1, tt);
                float v2 = adjval(dq.y,  fp, opn, q2, tt);
                float v3 = adjval(dq.z,  fp, opn, q3, tt);

                const unsigned du = (unsigned)(i - j0);   // diagonal patch
                if (du < 4u) {
                    if      (du == 0u) v0 = 1.0f;
                    else if (du == 1u) v1 = 1.0f;
                    else if (du == 2u) v2 = 1.0f;
                    else               v3 = 1.0f;
                }
                *reinterpret_cast<float4*>(
                    out + OFF_ADJ + ((long long)(b * N_ + i)) * N_ + j0) =
                    make_float4(v0, v1, v2, v3);
            } else {
                // Straggler columns j = 0,1,2 (dq.x/y/z) and j = 1023 (dprev)
                float v0 = adjval(dq.x,  fp, opn, q0, tt);
                float v1 = adjval(dq.y,  fp, opn, q1, tt);
                float v2 = adjval(dq.z,  fp, opn, q2, tt);
                float v3 = adjval(dprev, fp, opn, q3, tt);
                if (i == 0)      v0 = 1.0f;
                if (i == 1)      v1 = 1.0f;
                if (i == 2)      v2 = 1.0f;
                if (i == N_ - 1) v3 = 1.0f;
                float* ro = out + OFF_ADJ + ((long long)(b * N_ + i)) * N_;
                ro[0] = v0; ro[1] = v1; ro[2] = v2; ro[N_ - 1] = v3;
            }
        }
    }
}

// ---------------------------------------------------------------------------
extern "C" void kernel_launch(void* const* d_in, const int* in_sizes, int n_in,
                              void* d_out, int out_size)
{
    (void)in_sizes; (void)n_in; (void)out_size;
    const float* inputs = (const float*)d_in[0];
    const float* dist   = (const float*)d_in[1];
    const float* mask   = (const float*)d_in[2];
    const float* ptime  = (const float*)d_in[3];
    const int*   pres   = (const int*)d_in[4];
    const int*   fut    = (const int*)d_in[5];
    float* out = (float*)d_out;

    bs_prep<<<B_, 256>>>((const float4*)inputs, dist, mask, ptime, pres, fut, out);
    bs_done<<<1, B_>>>(out);
    bs_adj<<<dim3(N_ / TI, B_ / BG), 256>>>(dist, inputs, out);
}

// round 9
// speedup vs baseline: 1.5037x; 1.5037x over previous
#include <cuda_runtime.h>

// BeamSearch_11295763988573 — GB300 (sm_103a)
//
// Output layout (float32, tuple flattened in order):
//   [0]                                   done        (1 elem)
//   [1, 1+B*N)                            new_mask    (B,N)
//   [1+B*N, 1+B*N+B*N*N)                  adj         (B,N,N)
//   then future_actions (B), present_time_new (B), step_mask (B)

static constexpr int B_ = 64;
static constexpr int N_ = 1024;
static constexpr int TI = 16;   // i-rows per block in adj kernel
static constexpr int BG = 4;    // b's per block in adj kernel (small => high occupancy)

static constexpr long long OFF_NM  = 1;
static constexpr long long OFF_ADJ = 1 + (long long)B_ * N_;                 // 65537
static constexpr long long OFF_FA  = OFF_ADJ + (long long)B_ * N_ * N_;      // 67174401
static constexpr long long OFF_PT  = OFF_FA + B_;
static constexpr long long OFF_SM  = OFF_PT + B_;

// Per-(b,j) constants for the adj kernel: {closing, durat, dlast, new_mask}
__device__ float4 g_q[B_ * N_];
// Per-(b,i) constants: {fpresent, opening}
__device__ float2 g_fo[B_ * N_];

// ---------------------------------------------------------------------------
// Kernel 1: new_mask, fpresent, per-j constants, small outputs.
// Exact elementwise reproduction of the reference arithmetic.
// grid = (B, 4): blockIdx.y selects a 256-wide j slice.
// ---------------------------------------------------------------------------
__global__ __launch_bounds__(256) void bs_prep(
    const float4* __restrict__ inp4,   // (B,N,4): x=open, y=close, z=dur, w=ttime
    const float*  __restrict__ dist,   // (N,N)
    const float*  __restrict__ mask,   // (B,N)
    const float*  __restrict__ ptime,  // (B,1)
    const int*    __restrict__ pres,   // (B,)
    const int*    __restrict__ fut,    // (B,)
    float* __restrict__ out)
{
    const int b  = blockIdx.x;
    const int pa = pres[b];
    const float pt = ptime[b];
    const float tt0 = __ldg(reinterpret_cast<const float*>(inp4) + 3); // inputs[0,0,ARR]

    const int j = blockIdx.y * 256 + threadIdx.x;
    {
        const float4 in = inp4[b * N_ + j];
        const float arrive = __ldg(&dist[pa * N_ + j]) + pt;
        const float wait   = fmaxf(0.0f, in.x - arrive);
        const float s1     = arrive + wait;                 // arrive + wait (ref order)
        const float dl     = __ldg(&dist[j * N_ + (N_ - 1)]);
        const bool c1 = (s1 <= in.y);
        const bool c2 = (((s1 + in.z) + dl) <= tt0);        // ((arr+wait)+dur)+dlast <= tt
        float m = mask[b * N_ + j];
        if (j == pa) m = 0.0f;
        const float nm = (c1 && c2) ? m : 0.0f;

        out[OFF_NM + (long long)b * N_ + j] = nm;
        g_q [b * N_ + j] = make_float4(in.y, in.z, dl, nm);
        g_fo[b * N_ + j] = make_float2(s1 + in.z, in.x);    // fpresent, opening
    }

    if (threadIdx.x == 0 && blockIdx.y == 0) {
        const int fa = fut[b];
        const float4 infa = inp4[b * N_ + fa];
        const float arrj = __ldg(&dist[pa * N_ + fa]) + pt;
        const float wj   = fmaxf(0.0f, infa.x - arrj);
        out[OFF_FA + b] = (float)fa;
        out[OFF_PT + b] = (arrj + wj) + infa.z;
        out[OFF_SM + b] = 1.0f;
    }
}

// ---------------------------------------------------------------------------
// Kernel: done = !any(new_mask[:, -1] > 0)
// ---------------------------------------------------------------------------
__global__ void bs_done(float* __restrict__ out)
{
    const int b = threadIdx.x;  // 64 threads
    const int v = (out[OFF_NM + (long long)b * N_ + (N_ - 1)] > 0.0f) ? 1 : 0;
    const int any = __syncthreads_or(v);
    if (b == 0) out[0] = any ? 0.0f : 1.0f;
}

// ---------------------------------------------------------------------------
// Kernel 2: adj (B,N,N). HBM-write-bound.
// adj[b,i,j] = (i==j) ? 1 : new_mask[b,j] * a1 * a2, with
//   arr2 = dist[i,j] + fpresent[b,i]
//   s    = fmax(arr2, open[b,i])       (outcome-exact vs arr2 + max(0, open-arr2))
//   a1   = s <= close[b,j]
//   a2   = ((s + dur[b,j]) + dlast[j]) <= ttime[b]
//
// Alignment: out base for adj is ≡ 4 bytes (mod 16), so thread t owns the
// ALIGNED output quad j∈[4t+3, 4t+7). Its dist values come from the aligned
// quad [4t+4,4t+8) plus d[4t+3] via __shfl_up from the neighbor lane.
// Thread 255 handles straggler columns {0,1,2,1023}.
// Stores use __stcs (streaming) so the 256MB write stream does not evict the
// small dist/q read sets from L2.
// ---------------------------------------------------------------------------
__device__ __forceinline__ float adjval(float d, float fp, float opn,
                                        float4 q, float tt)
{
    const float arr2 = d + fp;
    const float s    = fmaxf(arr2, opn);
    const float s2   = (s + q.y) + q.z;
    return (s <= q.x && s2 <= tt) ? q.w : 0.0f;
}

__global__ __launch_bounds__(256) void bs_adj(
    const float* __restrict__ dist,
    const float* __restrict__ inpf,    // raw float view of inputs
    float* __restrict__ out)
{
    const int t   = threadIdx.x;            // 0..255
    const int ib0 = blockIdx.x * TI;
    const int b0  = blockIdx.y * BG;
    const bool main_thr = (t < 255);
    const int j0 = 4 * t + 3;               // first owned output column (t<255)

#pragma unroll
    for (int bb = 0; bb < BG; ++bb) {
        const int b = b0 + bb;
        const float tt = __ldg(inpf + (long long)b * N_ * 4 + 3);  // inputs[b,0,ARR]

        float4 q0, q1, q2, q3;
        if (main_thr) {
            q0 = g_q[b * N_ + j0];
            q1 = g_q[b * N_ + j0 + 1];
            q2 = g_q[b * N_ + j0 + 2];
            q3 = g_q[b * N_ + j0 + 3];
        } else {
            q0 = g_q[b * N_ + 0];
            q1 = g_q[b * N_ + 1];
            q2 = g_q[b * N_ + 2];
            q3 = g_q[b * N_ + N_ - 1];
        }

        float* __restrict__ orow_base = out + OFF_ADJ + (long long)b * N_ * N_;

#pragma unroll 4
        for (int ii = 0; ii < TI; ++ii) {
            const int i = ib0 + ii;
            const float2 fo = g_fo[b * N_ + i];
            const float fp = fo.x, opn = fo.y;

            float4 dq;
            if (main_thr) {
                dq = *reinterpret_cast<const float4*>(dist + (long long)i * N_ + 4 * t + 4);
            } else {
                dq = *reinterpret_cast<const float4*>(dist + (long long)i * N_);  // d[0..3]
            }
            // d[4t+3] lives in the previous lane's quad (.w). Lane31's value
            // conveniently is d[1023] for thread 255.
            float dprev = __shfl_up_sync(0xFFFFFFFFu, dq.w, 1);

            if (main_thr) {
                if ((t & 31) == 0)  // warp-edge lane: fetch d[4t+3] directly
                    dprev = __ldg(dist + (long long)i * N_ + j0);

                float v0 = adjval(dprev, fp, opn, q0, tt);
                float v1 = adjval(dq.x,  fp, opn, q1, tt);
                float v2 = adjval(dq.y,  fp, opn, q2, tt);
                float v3 = adjval(dq.z,  fp, opn, q3, tt);

                const unsigned du = (unsigned)(i - j0);   // diagonal patch
                if (du < 4u) {
                    if      (du == 0u) v0 = 1.0f;
                    else if (du == 1u) v1 = 1.0f;
                    else if (du == 2u) v2 = 1.0f;
                    else               v3 = 1.0f;
                }
                __stcs(reinterpret_cast<float4*>(orow_base + (long long)i * N_ + j0),
                       make_float4(v0, v1, v2, v3));
            } else {
                // Straggler columns j = 0,1,2 (dq.x/y/z) and j = 1023 (dprev)
                float v0 = adjval(dq.x,  fp, opn, q0, tt);
                float v1 = adjval(dq.y,  fp, opn, q1, tt);
                float v2 = adjval(dq.z,  fp, opn, q2, tt);
                float v3 = adjval(dprev, fp, opn, q3, tt);
                if (i == 0)      v0 = 1.0f;
                if (i == 1)      v1 = 1.0f;
                if (i == 2)      v2 = 1.0f;
                if (i == N_ - 1) v3 = 1.0f;
                float* ro = orow_base + (long long)i * N_;
                __stcs(ro,          v0);
                __stcs(ro + 1,      v1);
                __stcs(ro + 2,      v2);
                __stcs(ro + N_ - 1, v3);
            }
        }
    }
}

// ---------------------------------------------------------------------------
extern "C" void kernel_launch(void* const* d_in, const int* in_sizes, int n_in,
                              void* d_out, int out_size)
{
    (void)in_sizes; (void)n_in; (void)out_size;
    const float* inputs = (const float*)d_in[0];
    const float* dist   = (const float*)d_in[1];
    const float* mask   = (const float*)d_in[2];
    const float* ptime  = (const float*)d_in[3];
    const int*   pres   = (const int*)d_in[4];
    const int*   fut    = (const int*)d_in[5];
    float* out = (float*)d_out;

    bs_prep<<<dim3(B_, 4), 256>>>((const float4*)inputs, dist, mask, ptime, pres, fut, out);
    bs_done<<<1, B_>>>(out);
    bs_adj<<<dim3(N_ / TI, B_ / BG), 256>>>(dist, inputs, out);
}

// round 10
// speedup vs baseline: 1.5072x; 1.0023x over previous
#include <cuda_runtime.h>

// BeamSearch_11295763988573 — GB300 (sm_103a)
//
// Output layout (float32, tuple flattened in order):
//   [0]                                   done        (1 elem)
//   [1, 1+B*N)                            new_mask    (B,N)
//   [1+B*N, 1+B*N+B*N*N)                  adj         (B,N,N)
//   then future_actions (B), present_time_new (B), step_mask (B)

static constexpr int B_ = 64;
static constexpr int N_ = 1024;
static constexpr int TI = 16;   // i-rows per block in adj kernel
static constexpr int BG = 4;    // b's per block in adj kernel (small => high occupancy)

static constexpr long long OFF_NM  = 1;
static constexpr long long OFF_ADJ = 1 + (long long)B_ * N_;                 // 65537
static constexpr long long OFF_FA  = OFF_ADJ + (long long)B_ * N_ * N_;      // 67174401
static constexpr long long OFF_PT  = OFF_FA + B_;
static constexpr long long OFF_SM  = OFF_PT + B_;

// Per-(b,j) constants for the adj kernel: {closing, durat, dlast, new_mask}
__device__ float4 g_q[B_ * N_];
// Per-(b,i) constants: {fpresent, opening}
__device__ float2 g_fo[B_ * N_];

// ---------------------------------------------------------------------------
// Kernel 1: new_mask, fpresent, per-j constants, small outputs.
// Exact elementwise reproduction of the reference arithmetic.
// grid = (B, 4): blockIdx.y selects a 256-wide j slice.
// ---------------------------------------------------------------------------
__global__ __launch_bounds__(256) void bs_prep(
    const float4* __restrict__ inp4,   // (B,N,4): x=open, y=close, z=dur, w=ttime
    const float*  __restrict__ dist,   // (N,N)
    const float*  __restrict__ mask,   // (B,N)
    const float*  __restrict__ ptime,  // (B,1)
    const int*    __restrict__ pres,   // (B,)
    const int*    __restrict__ fut,    // (B,)
    float* __restrict__ out)
{
    const int b  = blockIdx.x;
    const int pa = pres[b];
    const float pt = ptime[b];
    const float tt0 = __ldg(reinterpret_cast<const float*>(inp4) + 3); // inputs[0,0,ARR]

    const int j = blockIdx.y * 256 + threadIdx.x;
    {
        const float4 in = inp4[b * N_ + j];
        const float arrive = __ldg(&dist[pa * N_ + j]) + pt;
        const float wait   = fmaxf(0.0f, in.x - arrive);
        const float s1     = arrive + wait;                 // arrive + wait (ref order)
        const float dl     = __ldg(&dist[j * N_ + (N_ - 1)]);
        const bool c1 = (s1 <= in.y);
        const bool c2 = (((s1 + in.z) + dl) <= tt0);        // ((arr+wait)+dur)+dlast <= tt
        float m = mask[b * N_ + j];
        if (j == pa) m = 0.0f;
        const float nm = (c1 && c2) ? m : 0.0f;

        out[OFF_NM + (long long)b * N_ + j] = nm;
        g_q [b * N_ + j] = make_float4(in.y, in.z, dl, nm);
        g_fo[b * N_ + j] = make_float2(s1 + in.z, in.x);    // fpresent, opening
    }

    if (threadIdx.x == 0 && blockIdx.y == 0) {
        const int fa = fut[b];
        const float4 infa = inp4[b * N_ + fa];
        const float arrj = __ldg(&dist[pa * N_ + fa]) + pt;
        const float wj   = fmaxf(0.0f, infa.x - arrj);
        out[OFF_FA + b] = (float)fa;
        out[OFF_PT + b] = (arrj + wj) + infa.z;
        out[OFF_SM + b] = 1.0f;
    }
}

// ---------------------------------------------------------------------------
// Kernel: done = !any(new_mask[:, -1] > 0)
// ---------------------------------------------------------------------------
__global__ void bs_done(float* __restrict__ out)
{
    const int b = threadIdx.x;  // 64 threads
    const int v = (out[OFF_NM + (long long)b * N_ + (N_ - 1)] > 0.0f) ? 1 : 0;
    const int any = __syncthreads_or(v);
    if (b == 0) out[0] = any ? 0.0f : 1.0f;
}

// ---------------------------------------------------------------------------
// Kernel 2: adj (B,N,N). HBM-write-bound.
// adj[b,i,j] = (i==j) ? 1 : new_mask[b,j] * a1 * a2, with
//   arr2 = dist[i,j] + fpresent[b,i]
//   s    = fmax(arr2, open[b,i])       (outcome-exact vs arr2 + max(0, open-arr2))
//   a1   = s <= close[b,j]
//   a2   = ((s + dur[b,j]) + dlast[j]) <= ttime[b]
//
// Alignment: out base for adj is ≡ 4 bytes (mod 16), so thread t owns the
// ALIGNED output quad j∈[4t+3, 4t+7). Its dist values come from the aligned
// quad [4t+4,4t+8) plus d[4t+3] via __shfl_up from the neighbor lane.
// Thread 255 handles straggler columns {0,1,2,1023}.
// Stores use __stcs (streaming) so the 256MB write stream does not evict the
// small dist/q read sets from L2.
// ---------------------------------------------------------------------------
__device__ __forceinline__ float adjval(float d, float fp, float opn,
                                        float4 q, float tt)
{
    const float arr2 = d + fp;
    const float s    = fmaxf(arr2, opn);
    const float s2   = (s + q.y) + q.z;
    return (s <= q.x && s2 <= tt) ? q.w : 0.0f;
}

__global__ __launch_bounds__(256) void bs_adj(
    const float* __restrict__ dist,
    const float* __restrict__ inpf,    // raw float view of inputs
    float* __restrict__ out)
{
    const int t   = threadIdx.x;            // 0..255
    const int ib0 = blockIdx.x * TI;
    const int b0  = blockIdx.y * BG;
    const bool main_thr = (t < 255);
    const int j0 = 4 * t + 3;               // first owned output column (t<255)

#pragma unroll
    for (int bb = 0; bb < BG; ++bb) {
        const int b = b0 + bb;
        const float tt = __ldg(inpf + (long long)b * N_ * 4 + 3);  // inputs[b,0,ARR]

        float4 q0, q1, q2, q3;
        if (main_thr) {
            q0 = g_q[b * N_ + j0];
            q1 = g_q[b * N_ + j0 + 1];
            q2 = g_q[b * N_ + j0 + 2];
            q3 = g_q[b * N_ + j0 + 3];
        } else {
            q0 = g_q[b * N_ + 0];
            q1 = g_q[b * N_ + 1];
            q2 = g_q[b * N_ + 2];
            q3 = g_q[b * N_ + N_ - 1];
        }

        float* __restrict__ orow_base = out + OFF_ADJ + (long long)b * N_ * N_;

#pragma unroll 4
        for (int ii = 0; ii < TI; ++ii) {
            const int i = ib0 + ii;
            const float2 fo = g_fo[b * N_ + i];
            const float fp = fo.x, opn = fo.y;

            float4 dq;
            if (main_thr) {
                dq = *reinterpret_cast<const float4*>(dist + (long long)i * N_ + 4 * t + 4);
            } else {
                dq = *reinterpret_cast<const float4*>(dist + (long long)i * N_);  // d[0..3]
            }
            // d[4t+3] lives in the previous lane's quad (.w). Lane31's value
            // conveniently is d[1023] for thread 255.
            float dprev = __shfl_up_sync(0xFFFFFFFFu, dq.w, 1);

            if (main_thr) {
                if ((t & 31) == 0)  // warp-edge lane: fetch d[4t+3] directly
                    dprev = __ldg(dist + (long long)i * N_ + j0);

                float v0 = adjval(dprev, fp, opn, q0, tt);
                float v1 = adjval(dq.x,  fp, opn, q1, tt);
                float v2 = adjval(dq.y,  fp, opn, q2, tt);
                float v3 = adjval(dq.z,  fp, opn, q3, tt);

                const unsigned du = (unsigned)(i - j0);   // diagonal patch
                if (du < 4u) {
                    if      (du == 0u) v0 = 1.0f;
                    else if (du == 1u) v1 = 1.0f;
                    else if (du == 2u) v2 = 1.0f;
                    else               v3 = 1.0f;
                }
                __stcs(reinterpret_cast<float4*>(orow_base + (long long)i * N_ + j0),
                       make_float4(v0, v1, v2, v3));
            } else {
                // Straggler columns j = 0,1,2 (dq.x/y/z) and j = 1023 (dprev)
                float v0 = adjval(dq.x,  fp, opn, q0, tt);
                float v1 = adjval(dq.y,  fp, opn, q1, tt);
                float v2 = adjval(dq.z,  fp, opn, q2, tt);
                float v3 = adjval(dprev, fp, opn, q3, tt);
                if (i == 0)      v0 = 1.0f;
                if (i == 1)      v1 = 1.0f;
                if (i == 2)      v2 = 1.0f;
                if (i == N_ - 1) v3 = 1.0f;
                float* ro = orow_base + (long long)i * N_;
                __stcs(ro,          v0);
                __stcs(ro + 1,      v1);
                __stcs(ro + 2,      v2);
                __stcs(ro + N_ - 1, v3);
            }
        }
    }
}

// ---------------------------------------------------------------------------
extern "C" void kernel_launch(void* const* d_in, const int* in_sizes, int n_in,
                              void* d_out, int out_size)
{
    (void)in_sizes; (void)n_in; (void)out_size;
    const float* inputs = (const float*)d_in[0];
    const float* dist   = (const float*)d_in[1];
    const float* mask   = (const float*)d_in[2];
    const float* ptime  = (const float*)d_in[3];
    const int*   pres   = (const int*)d_in[4];
    const int*   fut    = (const int*)d_in[5];
    float* out = (float*)d_out;

    bs_prep<<<dim3(B_, 4), 256>>>((const float4*)inputs, dist, mask, ptime, pres, fut, out);
    bs_done<<<1, B_>>>(out);
    bs_adj<<<dim3(N_ / TI, B_ / BG), 256>>>(dist, inputs, out);
}